// round 10
// baseline (speedup 1.0000x reference)
#include <cuda_runtime.h>
#include <cuda_bf16.h>

#define NBLK 1036   // 148 SMs * 7 resident blocks -> exactly one wave
#define NTHR 256

__device__ float g_partial[NBLK];
__device__ unsigned int g_count = 0;

typedef unsigned long long u64;

__device__ __forceinline__ float fast_lg2(float x) {
    float r; asm("lg2.approx.f32 %0, %1;" : "=f"(r) : "f"(x)); return r;
}
__device__ __forceinline__ float fast_ex2(float x) {
    float r; asm("ex2.approx.f32 %0, %1;" : "=f"(r) : "f"(x)); return r;
}
__device__ __forceinline__ float fast_sqrt(float x) {
    float r; asm("sqrt.approx.f32 %0, %1;" : "=f"(r) : "f"(x)); return r;
}

// ---- packed f32x2 helpers (sm_103) ----
__device__ __forceinline__ u64 pk2(float a, float b) {
    u64 r; asm("mov.b64 %0, {%1, %2};" : "=l"(r) : "f"(a), "f"(b)); return r;
}
__device__ __forceinline__ void upk2(float& a, float& b, u64 v) {
    asm("mov.b64 {%0, %1}, %2;" : "=f"(a), "=f"(b) : "l"(v));
}
__device__ __forceinline__ u64 f2fma(u64 a, u64 b, u64 c) {
    u64 r; asm("fma.rn.f32x2 %0, %1, %2, %3;" : "=l"(r) : "l"(a), "l"(b), "l"(c)); return r;
}
__device__ __forceinline__ u64 f2mul(u64 a, u64 b) {
    u64 r; asm("mul.rn.f32x2 %0, %1, %2;" : "=l"(r) : "l"(a), "l"(b)); return r;
}
__device__ __forceinline__ u64 f2add(u64 a, u64 b) {
    u64 r; asm("add.rn.f32x2 %0, %1, %2;" : "=l"(r) : "l"(a), "l"(b)); return r;
}
__device__ __forceinline__ u64 bc(float x) { return pk2(x, x); }

// Loss evaluated directly at the polynomial initializer w0 — the loss is
// stationary in w at the true Lambert-W root, so error = O(|w0-W|^2) ~ 3e-7.
// loss = lmt * e^{-w0} + 0.9*w0^2 ; rho-clamp at 0 makes the BCE clamp exact.
__device__ __forceinline__ void superloss_pair(float p0, float p1, float t0, float t1,
                                               u64& d_acc) {
    const u64 C_M1    = bc(-1.0f);
    const u64 C_LN2   = bc(0.69314718055994531f);
    const u64 C_MLN2  = bc(-0.69314718055994531f);
    const u64 C_M15   = bc(-1.5f);
    const u64 C_R2C   = bc(3.02031314273227248f);   // 2e/1.8
    const u64 C_2     = bc(2.0f);
    const u64 C_ML2E  = bc(-1.44269504088896341f);
    const u64 C_09    = bc(0.9f);
    const u64 C_P6 = bc(2.72851e-5f);
    const u64 C_P5 = bc(-6.43946e-4f);
    const u64 C_P4 = bc(6.307194e-3f);
    const u64 C_P3 = bc(-3.4116882e-2f);
    const u64 C_P2 = bc(0.118663595f);
    const u64 C_P1 = bc(-0.322237288f);
    const u64 C_P0 = bc(1.0f);

    float a0 = fast_lg2(p0),        a1 = fast_lg2(p1);
    float b0 = fast_lg2(1.0f - p0), b1 = fast_lg2(1.0f - p1);

    u64 d_lp  = pk2(a0, a1);
    u64 d_l1p = pk2(b0, b1);
    u64 d_t   = pk2(t0, t1);

    u64 d_diff = f2fma(d_lp, C_M1, d_l1p);
    u64 d_tl   = f2mul(d_t, C_LN2);
    u64 d_cc   = f2fma(d_l1p, C_MLN2, C_M15);
    u64 d_lmt  = f2fma(d_tl, d_diff, d_cc);

    u64 d_r2 = f2fma(d_lmt, C_R2C, C_2);
    float r20, r21; upk2(r20, r21, d_r2);
    float s0 = fast_sqrt(fmaxf(r20, 0.0f));
    float s1 = fast_sqrt(fmaxf(r21, 0.0f));
    u64 d_rho = pk2(s0, s1);

    u64 h = f2fma(C_P6, d_rho, C_P5);
    h = f2fma(h, d_rho, C_P4);
    h = f2fma(h, d_rho, C_P3);
    h = f2fma(h, d_rho, C_P2);
    h = f2fma(h, d_rho, C_P1);
    h = f2fma(h, d_rho, C_P0);
    u64 d_u = f2mul(d_rho, h);
    u64 d_w = f2add(d_u, C_M1);

    u64 d_wl = f2mul(d_w, C_ML2E);
    float wl0, wl1; upk2(wl0, wl1, d_wl);
    float e0 = fast_ex2(wl0), e1 = fast_ex2(wl1);
    u64 d_sig = pk2(e0, e1);

    u64 d_w2  = f2mul(d_w, d_w);
    u64 d_w29 = f2mul(d_w2, C_09);
    u64 d_ls  = f2fma(d_lmt, d_sig, d_w29);
    d_acc = f2add(d_acc, d_ls);
}

__device__ __forceinline__ float superloss_scalar(float p, float t) {
    const float LN2 = 0.69314718055994531f;
    const float L2E = 1.44269504088896341f;

    float lp2  = fast_lg2(p);
    float l1p2 = fast_lg2(1.0f - p);
    float nl2 = fmaf(t, l1p2 - lp2, -l1p2);
    float lmt = fmaf(LN2, nl2, -1.5f);
    float r2 = fmaf(lmt, 3.02031314273227f, 2.0f);
    float rho = fast_sqrt(fmaxf(r2, 0.0f));
    float h = fmaf(rho, 2.72851e-5f, -6.43946e-4f);
    h = fmaf(h, rho,  6.307194e-3f);
    h = fmaf(h, rho, -3.4116882e-2f);
    h = fmaf(h, rho,  0.118663595f);
    h = fmaf(h, rho, -0.322237288f);
    h = fmaf(h, rho,  1.0f);
    float w = fmaf(rho, h, -1.0f);
    float sig = fast_ex2(-w * L2E);
    return fmaf(lmt, sig, 0.9f * w * w);
}

__global__ void __launch_bounds__(NTHR, 7)
superloss_fused(const float* __restrict__ logits,
                const float* __restrict__ targets,
                float* __restrict__ out,
                int n) {
    int tid = threadIdx.x;
    int gtid = blockIdx.x * NTHR + tid;
    int nv = n >> 2;
    int stride = NBLK * NTHR;

    const float4* lp4 = reinterpret_cast<const float4*>(logits);
    const float4* tp4 = reinterpret_cast<const float4*>(targets);

    u64 d_acc = bc(0.0f);

    // Software-pipelined grid-stride loop: iteration k+1's loads are issued
    // before iteration k's compute, so the ~600cyc DRAM latency hides behind
    // a full iteration of MUFU/FMA work in the same warp.
    int i = gtid;
    bool valid = (i < nv);
    float4 p_cur, t_cur;
    if (valid) { p_cur = __ldcs(lp4 + i); t_cur = __ldcs(tp4 + i); }
    while (valid) {
        int j = i + stride;
        bool vnext = (j < nv);
        float4 p_nxt, t_nxt;
        if (vnext) { p_nxt = __ldcs(lp4 + j); t_nxt = __ldcs(tp4 + j); }

        superloss_pair(p_cur.x, p_cur.y, t_cur.x, t_cur.y, d_acc);
        superloss_pair(p_cur.z, p_cur.w, t_cur.z, t_cur.w, d_acc);

        p_cur = p_nxt; t_cur = t_nxt;
        i = j; valid = vnext;
    }

    float acc0, acc1; upk2(acc0, acc1, d_acc);
    int tail_start = nv << 2;
    for (int k = tail_start + gtid; k < n; k += stride)
        acc0 += superloss_scalar(logits[k], targets[k]);

    float acc = acc0 + acc1;

    __shared__ float s[NTHR];
    __shared__ bool is_last;
    s[tid] = acc;
    __syncthreads();
#pragma unroll
    for (int o = NTHR / 2; o > 0; o >>= 1) {
        if (tid < o) s[tid] += s[tid + o];
        __syncthreads();
    }
    if (tid == 0) {
        g_partial[blockIdx.x] = s[0];
        __threadfence();
        unsigned int prev = atomicInc(&g_count, NBLK - 1);
        is_last = (prev == NBLK - 1);
    }
    __syncthreads();

    if (is_last) {
        __threadfence();
        volatile float* gp = g_partial;
        float a = 0.0f;
        for (int j = tid; j < NBLK; j += NTHR) a += gp[j];
        s[tid] = a;
        __syncthreads();
#pragma unroll
        for (int o = NTHR / 2; o > 0; o >>= 1) {
            if (tid < o) s[tid] += s[tid + o];
            __syncthreads();
        }
        if (tid == 0) out[0] = s[0] * (1.0f / 32.0f);
    }
}

extern "C" void kernel_launch(void* const* d_in, const int* in_sizes, int n_in,
                              void* d_out, int out_size) {
    const float* logits  = (const float*)d_in[0];
    const float* targets = (const float*)d_in[1];
    float* out = (float*)d_out;
    int n = in_sizes[0];

    superloss_fused<<<NBLK, NTHR>>>(logits, targets, out, n);
}

// round 11
// speedup vs baseline: 1.0783x; 1.0783x over previous
#include <cuda_runtime.h>
#include <cuda_bf16.h>

#define NBLK 1184
#define NTHR 256

__device__ float g_partial[NBLK];
__device__ unsigned int g_count = 0;

typedef unsigned long long u64;

__device__ __forceinline__ float fast_lg2(float x) {
    float r; asm("lg2.approx.f32 %0, %1;" : "=f"(r) : "f"(x)); return r;
}
__device__ __forceinline__ float fast_sqrt(float x) {
    float r; asm("sqrt.approx.f32 %0, %1;" : "=f"(r) : "f"(x)); return r;
}

// ---- packed f32x2 helpers (sm_103) ----
__device__ __forceinline__ u64 pk2(float a, float b) {
    u64 r; asm("mov.b64 %0, {%1, %2};" : "=l"(r) : "f"(a), "f"(b)); return r;
}
__device__ __forceinline__ void upk2(float& a, float& b, u64 v) {
    asm("mov.b64 {%0, %1}, %2;" : "=f"(a), "=f"(b) : "l"(v));
}
__device__ __forceinline__ u64 f2fma(u64 a, u64 b, u64 c) {
    u64 r; asm("fma.rn.f32x2 %0, %1, %2, %3;" : "=l"(r) : "l"(a), "l"(b), "l"(c)); return r;
}
__device__ __forceinline__ u64 f2mul(u64 a, u64 b) {
    u64 r; asm("mul.rn.f32x2 %0, %1, %2;" : "=l"(r) : "l"(a), "l"(b)); return r;
}
__device__ __forceinline__ u64 f2add(u64 a, u64 b) {
    u64 r; asm("add.rn.f32x2 %0, %1, %2;" : "=l"(r) : "l"(a), "l"(b)); return r;
}
__device__ __forceinline__ u64 bc(float x) { return pk2(x, x); }

// Two elements, packed math, 3 MUFU per element (2 lg2 + sqrt).
// Fixed-point identity: at the root, sigma = w/y and lmt = 1.8y (unclamped),
// so loss = lmt*sigma + 0.9w^2 = 0.9*w*(w+2). Evaluated at the degree-6
// initializer w0 (|w0-W| <= ~3e-4, equioscillating), per-element error is
// 1.8(w+1)*delta -> sum error ~1e-4 relative. Clamped branch (y=-1/e, w=-1):
// loss = lmt*e + 0.9, selected on lmt; continuous at the boundary.
__device__ __forceinline__ void superloss_pair(float p0, float p1, float t0, float t1,
                                               u64& d_acc) {
    const float CLAMP_LMT = -0.66218299410859620f;  // 1.8 * (-1/e)

    const u64 C_M1    = bc(-1.0f);
    const u64 C_LN2   = bc(0.69314718055994531f);
    const u64 C_MLN2  = bc(-0.69314718055994531f);
    const u64 C_M15   = bc(-1.5f);
    const u64 C_R2C   = bc(3.02031314273227248f);   // 2e/1.8
    const u64 C_2     = bc(2.0f);
    const u64 C_09    = bc(0.9f);
    const u64 C_E     = bc(2.71828182845904523f);
    const u64 C_P6 = bc(2.72851e-5f);
    const u64 C_P5 = bc(-6.43946e-4f);
    const u64 C_P4 = bc(6.307194e-3f);
    const u64 C_P3 = bc(-3.4116882e-2f);
    const u64 C_P2 = bc(0.118663595f);
    const u64 C_P1 = bc(-0.322237288f);
    const u64 C_P0 = bc(1.0f);

    float a0 = fast_lg2(p0),        a1 = fast_lg2(p1);
    float b0 = fast_lg2(1.0f - p0), b1 = fast_lg2(1.0f - p1);

    u64 d_lp  = pk2(a0, a1);
    u64 d_l1p = pk2(b0, b1);
    u64 d_t   = pk2(t0, t1);

    // lmt = l - tau
    u64 d_diff = f2fma(d_lp, C_M1, d_l1p);
    u64 d_tl   = f2mul(d_t, C_LN2);
    u64 d_cc   = f2fma(d_l1p, C_MLN2, C_M15);
    u64 d_lmt  = f2fma(d_tl, d_diff, d_cc);

    // rho^2 = 2(1 + e*y) = lmt*(2e/1.8) + 2 ; clamp at 0 -> w0 = -1 exact
    u64 d_r2 = f2fma(d_lmt, C_R2C, C_2);
    float r20, r21; upk2(r20, r21, d_r2);
    float s0 = fast_sqrt(fmaxf(r20, 0.0f));
    float s1 = fast_sqrt(fmaxf(r21, 0.0f));
    u64 d_rho = pk2(s0, s1);

    // degree-6 init: w0 = -1 + rho*h(rho)
    u64 h = f2fma(C_P6, d_rho, C_P5);
    h = f2fma(h, d_rho, C_P4);
    h = f2fma(h, d_rho, C_P3);
    h = f2fma(h, d_rho, C_P2);
    h = f2fma(h, d_rho, C_P1);
    h = f2fma(h, d_rho, C_P0);
    u64 d_u = f2mul(d_rho, h);                // w0 + 1
    u64 d_w = f2add(d_u, C_M1);               // w0

    // unclamped: 0.9*w*(w+2) ; clamped: lmt*e + 0.9
    u64 d_wp2 = f2add(d_w, C_2);
    u64 d_w9  = f2mul(d_w, C_09);
    u64 d_lu  = f2mul(d_w9, d_wp2);
    u64 d_lc  = f2fma(d_lmt, C_E, C_09);

    float lu0, lu1; upk2(lu0, lu1, d_lu);
    float lc0, lc1; upk2(lc0, lc1, d_lc);
    float lm0, lm1; upk2(lm0, lm1, d_lmt);
    float r0 = (lm0 < CLAMP_LMT) ? lc0 : lu0;
    float r1 = (lm1 < CLAMP_LMT) ? lc1 : lu1;
    d_acc = f2add(d_acc, pk2(r0, r1));
}

__device__ __forceinline__ float superloss_scalar(float p, float t) {
    const float LN2 = 0.69314718055994531f;
    const float E   = 2.71828182845904523f;
    const float CLAMP_LMT = -0.66218299410859620f;

    float lp2  = fast_lg2(p);
    float l1p2 = fast_lg2(1.0f - p);
    float nl2 = fmaf(t, l1p2 - lp2, -l1p2);
    float lmt = fmaf(LN2, nl2, -1.5f);
    float r2 = fmaf(lmt, 3.02031314273227f, 2.0f);
    float rho = fast_sqrt(fmaxf(r2, 0.0f));
    float h = fmaf(rho, 2.72851e-5f, -6.43946e-4f);
    h = fmaf(h, rho,  6.307194e-3f);
    h = fmaf(h, rho, -3.4116882e-2f);
    h = fmaf(h, rho,  0.118663595f);
    h = fmaf(h, rho, -0.322237288f);
    h = fmaf(h, rho,  1.0f);
    float w = fmaf(rho, h, -1.0f);
    float lu = (0.9f * w) * (w + 2.0f);
    float lc = fmaf(lmt, E, 0.9f);
    return (lmt < CLAMP_LMT) ? lc : lu;
}

__global__ void __launch_bounds__(NTHR, 8)
superloss_fused(const float* __restrict__ logits,
                const float* __restrict__ targets,
                float* __restrict__ out,
                int n) {
    int tid = threadIdx.x;
    int gtid = blockIdx.x * NTHR + tid;
    int nv = n >> 2;
    int stride = NBLK * NTHR;

    const float4* lp4 = reinterpret_cast<const float4*>(logits);
    const float4* tp4 = reinterpret_cast<const float4*>(targets);

    u64 d_acc = bc(0.0f);
    for (int i = gtid; i < nv; i += stride) {
        float4 p4 = __ldcs(lp4 + i);
        float4 t4 = __ldcs(tp4 + i);
        superloss_pair(p4.x, p4.y, t4.x, t4.y, d_acc);
        superloss_pair(p4.z, p4.w, t4.z, t4.w, d_acc);
    }
    float acc0, acc1; upk2(acc0, acc1, d_acc);
    int tail_start = nv << 2;
    for (int k = tail_start + gtid; k < n; k += stride)
        acc0 += superloss_scalar(logits[k], targets[k]);

    float acc = acc0 + acc1;

    __shared__ float s[NTHR];
    __shared__ bool is_last;
    s[tid] = acc;
    __syncthreads();
#pragma unroll
    for (int o = NTHR / 2; o > 0; o >>= 1) {
        if (tid < o) s[tid] += s[tid + o];
        __syncthreads();
    }
    if (tid == 0) {
        g_partial[blockIdx.x] = s[0];
        __threadfence();
        unsigned int prev = atomicInc(&g_count, NBLK - 1);
        is_last = (prev == NBLK - 1);
    }
    __syncthreads();

    if (is_last) {
        __threadfence();
        volatile float* gp = g_partial;
        float a = 0.0f;
        for (int j = tid; j < NBLK; j += NTHR) a += gp[j];
        s[tid] = a;
        __syncthreads();
#pragma unroll
        for (int o = NTHR / 2; o > 0; o >>= 1) {
            if (tid < o) s[tid] += s[tid + o];
            __syncthreads();
        }
        if (tid == 0) out[0] = s[0] * (1.0f / 32.0f);
    }
}

extern "C" void kernel_launch(void* const* d_in, const int* in_sizes, int n_in,
                              void* d_out, int out_size) {
    const float* logits  = (const float*)d_in[0];
    const float* targets = (const float*)d_in[1];
    float* out = (float*)d_out;
    int n = in_sizes[0];

    superloss_fused<<<NBLK, NTHR>>>(logits, targets, out, n);
}